// round 13
// baseline (speedup 1.0000x reference)
#include <cuda_runtime.h>
#include <cuda_fp16.h>
#include <math.h>

#define DD 128
#define HH_ 128
#define WW_ 32
#define DHW (128*128*32)   // 524288 = 2^19
#define HW  (128*32)       // 4096
#define BB 2
#define EPSB 1e-5f

// ---------------- scratch (device globals; no allocations allowed) ----------------
__device__ float   g_occ[BB*DHW];
__device__ __align__(16) __half2 g_x1h[(size_t)BB*16*DHW];   // conv1 out, pair (c, c+8); bn applied in-place later
__device__ __align__(16) __half2 g_x2h[(size_t)BB*32*DHW];   // conv2 out, pair-interleaved
__device__ __align__(16) __half2 g_x3h[(size_t)BB*32*DHW];   // conv3 raw out (also sacrificial-profile scratch)
__device__ float g_min[6];
__device__ float g_sum[3][64];
__device__ float g_sumsq[3][64];
__device__ float g_scale[3][64];
__device__ float g_shift[3][64];

// split-fp16 weights, fragment layout. conv2 at 0, conv3 at W2_SZ.
#define W2_SZ (27*64*16)
#define W3_SZ (27*64*32)
__device__ unsigned int g_whi[W2_SZ + W3_SZ];
__device__ unsigned int g_wlo[W2_SZ + W3_SZ];

// ---------------- small helpers ----------------
__device__ __forceinline__ void cp16(unsigned int* dst_smem, const void* src_gmem) {
    unsigned int s = (unsigned int)__cvta_generic_to_shared(dst_smem);
    asm volatile("cp.async.cg.shared.global [%0], [%1], 16;" :: "r"(s), "l"(src_gmem));
}

__device__ __forceinline__ void mma_f16(float& c0, float& c1, float& c2, float& c3,
                                        unsigned int a0, unsigned int a1,
                                        unsigned int a2, unsigned int a3,
                                        unsigned int b0, unsigned int b1) {
    asm volatile("mma.sync.aligned.m16n8k16.row.col.f32.f16.f16.f32 "
                 "{%0,%1,%2,%3}, {%4,%5,%6,%7}, {%8,%9}, {%0,%1,%2,%3};"
                 : "+f"(c0), "+f"(c1), "+f"(c2), "+f"(c3)
                 : "r"(a0), "r"(a1), "r"(a2), "r"(a3), "r"(b0), "r"(b1));
}

// ---------------- zero occupancy + stats accumulators ----------------
__global__ void zero_kernel() {
    int t = blockIdx.x * blockDim.x + threadIdx.x;
    if (t < BB*DHW) g_occ[t] = 0.0f;
    if (t < 192) { g_sum[t/64][t%64] = 0.0f; g_sumsq[t/64][t%64] = 0.0f; }
}

// ---------------- per (b,dim) min over N points (NaN -> 0) ----------------
__global__ void min_kernel(const float* __restrict__ pc, int N) {
    __shared__ float s[256];
    int id = blockIdx.x;
    const float* p = pc + (size_t)id * N;
    float m = 1e30f;
    for (int i = threadIdx.x; i < N; i += 256) {
        float v = p[i];
        if (v != v) v = 0.0f;
        m = fminf(m, v);
    }
    s[threadIdx.x] = m; __syncthreads();
    for (int k = 128; k > 0; k >>= 1) {
        if (threadIdx.x < k) s[threadIdx.x] = fminf(s[threadIdx.x], s[threadIdx.x + k]);
        __syncthreads();
    }
    if (threadIdx.x == 0) g_min[id] = s[0];
}

// ---------------- scatter points into occupancy grid ----------------
__global__ void scatter_kernel(const float* __restrict__ pc, int N) {
    int t = blockIdx.x * blockDim.x + threadIdx.x;
    if (t >= BB * N) return;
    int b = t / N, j = t - b * N;
    const float* p = pc + (size_t)b * 3 * N;
    float x = p[j];       if (x != x) x = 0.0f;
    float y = p[N + j];   if (y != y) y = 0.0f;
    float z = p[2*N + j]; if (z != z) z = 0.0f;
    int ix = (int)floorf((x - g_min[b*3+0]) * 16.0f);
    int iy = (int)floorf((y - g_min[b*3+1]) * 16.0f);
    int iz = (int)floorf((z - g_min[b*3+2]) * 16.0f);
    ix = min(max(ix, 0), 127);
    iy = min(max(iy, 0), 127);
    iz = min(max(iz, 0), 31);
    g_occ[b*DHW + ix*HW + iy*WW_ + iz] = 1.0f;
}

// ---------------- conv1: 1 -> 32, fp32, fused stats, fp16 pair output ----------------
__global__ void conv1_kernel(const float* __restrict__ w1, const float* __restrict__ b1) {
    __shared__ float sIn[3][10][35];
    __shared__ float sW[27][32];
    __shared__ float sB[32];
    __shared__ float c1red[128];
    int d = blockIdx.x, h0 = blockIdx.y * 8, b = blockIdx.z;
    int tid = threadIdx.x;
    for (int i = tid; i < 32*27; i += 256) { int oc = i/27, tap = i%27; sW[tap][oc] = w1[i]; }
    if (tid < 32) sB[tid] = b1[tid];
    if (tid < 128) c1red[tid] = 0.0f;
    for (int i = tid; i < 3*10*34; i += 256) {
        int ww = i % 34; int r = i / 34; int hh = r % 10; int kd = r / 10;
        int gd = d + kd - 1, gh = h0 + hh - 1, gw = ww - 1;
        float v = 0.0f;
        if (gd >= 0 && gd < DD && gh >= 0 && gh < HH_ && gw >= 0 && gw < WW_)
            v = g_occ[b*DHW + gd*HW + gh*WW_ + gw];
        sIn[kd][hh][ww] = v;
    }
    __syncthreads();
    int tx = tid & 31, ty = tid >> 5;
    float acc[32];
    #pragma unroll
    for (int oc = 0; oc < 32; oc++) acc[oc] = sB[oc];
    #pragma unroll
    for (int kd = 0; kd < 3; kd++)
    #pragma unroll
    for (int kh = 0; kh < 3; kh++) {
        float a0 = sIn[kd][ty+kh][tx], a1 = sIn[kd][ty+kh][tx+1], a2 = sIn[kd][ty+kh][tx+2];
        int t0 = kd*9 + kh*3;
        #pragma unroll
        for (int oc = 0; oc < 32; oc++)
            acc[oc] = fmaf(a0, sW[t0][oc], fmaf(a1, sW[t0+1][oc], fmaf(a2, sW[t0+2][oc], acc[oc])));
    }
    size_t sp = (size_t)d*HW + (h0+ty)*WW_ + tx;
    #pragma unroll
    for (int cp = 0; cp < 16; cp++) {
        int ch = ((cp >> 3) << 4) + (cp & 7);
        g_x1h[(((size_t)(b*16 + cp)) << 19) + sp] = __floats2half2_rn(acc[ch], acc[ch + 8]);
    }
    #pragma unroll
    for (int oc = 0; oc < 32; oc++) {
        atomicAdd(&c1red[oc], acc[oc]);
        atomicAdd(&c1red[64 + oc], acc[oc]*acc[oc]);
    }
    __syncthreads();
    if (tid < 32) {
        atomicAdd(&g_sum[0][tid], c1red[tid]);
        atomicAdd(&g_sumsq[0][tid], c1red[64 + tid]);
    }
}

// ---------------- weight prep: fp32 -> split fp16 (hi+lo), fragment layout ----------------
// k within 16-chunk: k = 2*pp + e  <->  channel = kc*16 + pp + 8*e
// slot = kc*8 + (ppl%4)*2 + ppl/4  so LDG.64 at slot 2t gives pairs t and t+4
__global__ void prep_kernel(const float* __restrict__ w, int CIN, int base) {
    int t = blockIdx.x * blockDim.x + threadIdx.x;
    int CINP = CIN >> 1;
    int total = 27 * 64 * CINP;
    if (t >= total) return;
    int p   = t % CINP;
    int oc  = (t / CINP) % 64;
    int tap = t / (CINP * 64);
    int kc = p >> 3, ppl = p & 7;
    int slot = kc*8 + (ppl & 3)*2 + (ppl >> 2);
    int cl = kc*16 + ppl;
    int ch = cl + 8;
    float v0 = w[((size_t)oc*CIN + cl)*27 + tap];
    float v1 = w[((size_t)oc*CIN + ch)*27 + tap];
    __half h0 = __float2half_rn(v0);
    __half h1 = __float2half_rn(v1);
    __half l0 = __float2half_rn(v0 - __half2float(h0));
    __half l1 = __float2half_rn(v1 - __half2float(h1));
    unsigned int idx = base + (tap*64 + oc)*CINP + slot;
    __half2 hh = __halves2half2(h0, h1);
    __half2 ll = __halves2half2(l0, l1);
    g_whi[idx] = *reinterpret_cast<unsigned int*>(&hh);
    g_wlo[idx] = *reinterpret_cast<unsigned int*>(&ll);
}

// ---------------- standalone bn+relu (in-place on fp16 pair tensors) ----------------
__global__ void bnrelu_kernel(int stage) {
    __half2* x = (stage == 0) ? g_x1h : g_x2h;
    int CP = (stage == 0) ? 16 : 32;
    size_t t = (size_t)blockIdx.x * 256 + threadIdx.x;   // uint4 (=4 half2) index
    size_t total4 = ((size_t)BB * CP) << 17;
    if (t >= total4) return;
    int cp = (int)((t >> 17) % CP);
    int ca = ((cp >> 3) << 4) + (cp & 7), cb = ca + 8;
    float sa = g_scale[stage][ca], ha = g_shift[stage][ca];
    float sb = g_scale[stage][cb], hb = g_shift[stage][cb];
    uint4* p4 = reinterpret_cast<uint4*>(x) + t;
    uint4 raw = *p4;
    unsigned int* u = reinterpret_cast<unsigned int*>(&raw);
    #pragma unroll
    for (int i = 0; i < 4; i++) {
        __half2 v = *reinterpret_cast<__half2*>(&u[i]);
        float fa = fmaxf(fmaf(__low2float(v),  sa, ha), 0.0f);
        float fb = fmaxf(fmaf(__high2float(v), sb, hb), 0.0f);
        __half2 o = __floats2half2_rn(fa, fb);
        u[i] = *reinterpret_cast<unsigned int*>(&o);
    }
    *p4 = raw;
}

// ---------------- chunk fill: pure cp.async copies (input is post-bn fp16) ----------------
// buf layout: [plane 4][h 6][pair 8][40]; data at w-index gw+4 (gw 0..31), borders stay zero.
template<int CPIN>
__device__ __forceinline__ void fill_chunk(unsigned int* buf, const __half2* in,
                                           int b, int kk, int d0, int h0, int tid) {
    #pragma unroll
    for (int k = 0; k < 6; k++) {
        int i = tid + k*256;            // 0..1535
        int j = i & 7;                  // 16B chunk within row
        int r = i >> 3;                 // row 0..191
        int pp = r & 7;
        int hh = (r >> 3) % 6;
        int pd = r / 48;
        int gd = d0 - 1 + pd, gh = h0 + hh - 1;
        if ((unsigned)gd < DD && (unsigned)gh < HH_) {
            const __half2* src = in + (((size_t)(b*CPIN + kk*8 + pp)) << 19)
                                    + (size_t)gd*HW + gh*WW_ + j*4;
            cp16(buf + r*40 + 4 + j*4, src);
        }
    }
}

// ---------------- per-tap fragment load / MMA macros (register double-buffered) ----------------
// LOAD_TAP: B frags from smem (current chunk buffer `actb`), weight frags from L1/L2.
#define LOAD_TAP(T, BUF) do {                                                        \
    int kd_ = (T) / 9; int rr_ = (T) - kd_*9;                                        \
    int kh_ = rr_ / 3; int kw_ = rr_ - kh_*3;                                        \
    _Pragma("unroll")                                                                \
    for (int dsel_ = 0; dsel_ < 2; dsel_++) {                                        \
        const unsigned int* row_ = actb + ((dsel_ + kd_)*6 + hw + kh_)*320;          \
        _Pragma("unroll")                                                            \
        for (int nt_ = 0; nt_ < 4; nt_++) {                                          \
            int idx_ = bidx + nt_*8 + kw_;                                           \
            fb0[BUF][dsel_*4 + nt_] = row_[idx_];                                    \
            fb1[BUF][dsel_*4 + nt_] = row_[idx_ + 160];                              \
        }                                                                            \
    }                                                                                \
    _Pragma("unroll")                                                                \
    for (int mt_ = 0; mt_ < 2; mt_++) {                                              \
        unsigned int widx_ = wbase0 + (unsigned)(T)*(64*CPIN) + mt_*(16*CPIN);       \
        fah[BUF][mt_][0] = *(const uint2*)&g_whi[widx_];                             \
        fah[BUF][mt_][1] = *(const uint2*)&g_whi[widx_ + 8*CPIN];                    \
        fal[BUF][mt_][0] = *(const uint2*)&g_wlo[widx_];                             \
        fal[BUF][mt_][1] = *(const uint2*)&g_wlo[widx_ + 8*CPIN];                    \
    }                                                                                \
} while (0)

#define MMA_TAP(BUF) do {                                                            \
    _Pragma("unroll")                                                                \
    for (int mt_ = 0; mt_ < 2; mt_++)                                                \
        _Pragma("unroll")                                                            \
        for (int s_ = 0; s_ < 8; s_++) {                                             \
            float* A_ = acc[mt_][s_];                                                \
            mma_f16(A_[0], A_[1], A_[2], A_[3],                                      \
                    fah[BUF][mt_][0].x, fah[BUF][mt_][1].x,                          \
                    fah[BUF][mt_][0].y, fah[BUF][mt_][1].y,                          \
                    fb0[BUF][s_], fb1[BUF][s_]);                                     \
        }                                                                            \
    _Pragma("unroll")                                                                \
    for (int mt_ = 0; mt_ < 2; mt_++)                                                \
        _Pragma("unroll")                                                            \
        for (int s_ = 0; s_ < 8; s_++) {                                             \
            float* A_ = acc[mt_][s_];                                                \
            mma_f16(A_[0], A_[1], A_[2], A_[3],                                      \
                    fal[BUF][mt_][0].x, fal[BUF][mt_][1].x,                          \
                    fal[BUF][mt_][0].y, fal[BUF][mt_][1].y,                          \
                    fb0[BUF][s_], fb1[BUF][s_]);                                     \
        }                                                                            \
} while (0)

// ---------------- conv2/conv3: fp16 2-MMA implicit GEMM, 2 d-planes per CTA ----------------
// Block: (d0..d0+1, 4 h-rows, b), all 64 oc. 8 warps = 2 oc-warps x 4 h-warps.
// Tap-level software pipeline: register double-buffered fragments, prefetch tap t+1 under tap t MMAs.
// PROF=true: tiny sacrificial instance for ncu capture (launch idx 3) — writes to g_x3h scratch
// (fully overwritten by the real conv3 later), no stats atomics. Zero effect on results.
template<int CIN, bool PROF>
__global__ void __launch_bounds__(256) conv_mma(const float* __restrict__ bias) {
    constexpr int STAGE = (CIN == 32) ? 0 : 1;
    constexpr int CPIN  = CIN / 2;
    constexpr int NCH   = CIN / 16;
    constexpr int WBASE = (CIN == 32) ? 0 : W2_SZ;
    constexpr int BUFSZ = 4*6*8*40;                 // 7680 u32
    const __half2* in  = (CIN == 32) ? g_x1h : g_x2h;
    __half2*       outp = PROF ? g_x3h : ((CIN == 32) ? g_x2h : g_x3h);

    extern __shared__ unsigned int sAct[];          // [2][BUFSZ]
    __shared__ float sred[128];

    int d0 = blockIdx.x * 2;
    int h0 = blockIdx.y * 4;
    int b  = blockIdx.z;
    int tid = threadIdx.x, lane = tid & 31, wid = tid >> 5;
    int mw = wid & 1, hw = wid >> 1;
    int gQ = lane >> 2, tQ = lane & 3;
    int h = h0 + hw;
    int bidx = tQ*40 + gQ + 3;                      // B-frag base index within row

    // zero both buffers once (covers padding rows/borders forever)
    for (int i = tid; i < 2*BUFSZ; i += 256) sAct[i] = 0u;
    __syncthreads();

    // prologue: fill chunk 0 into buffer 0
    fill_chunk<CPIN>(sAct, in, b, 0, d0, h0, tid);
    asm volatile("cp.async.commit_group;" ::: "memory");
    asm volatile("cp.async.wait_group 0;" ::: "memory");
    __syncthreads();

    float acc[2][8][4];
    #pragma unroll
    for (int mt = 0; mt < 2; mt++)
        #pragma unroll
        for (int s = 0; s < 8; s++)
            #pragma unroll
            for (int k = 0; k < 4; k++) acc[mt][s][k] = 0.0f;

    // fragment double buffers
    unsigned int fb0[2][8], fb1[2][8];
    uint2 fah[2][2][2], fal[2][2][2];

    #pragma unroll 1
    for (int kk = 0; kk < NCH; kk++) {
        unsigned int* actb = sAct + (kk & 1) * BUFSZ;
        if (kk + 1 < NCH)
            fill_chunk<CPIN>(sAct + ((kk + 1) & 1) * BUFSZ, in, b, kk + 1, d0, h0, tid);
        asm volatile("cp.async.commit_group;" ::: "memory");

        unsigned int wbase0 = WBASE + (mw*32 + gQ)*CPIN + kk*8 + tQ*2;

        LOAD_TAP(0, 0);
        #pragma unroll 1
        for (int tt = 0; tt < 13; tt++) {
            int t = tt * 2;
            LOAD_TAP(t + 1, 1);
            MMA_TAP(0);
            if (t + 2 < 27) LOAD_TAP(t + 2, 0);
            MMA_TAP(1);
        }
        MMA_TAP(0);   // tap 26

        asm volatile("cp.async.wait_group 0;" ::: "memory");
        __syncthreads();
    }

    // ---- epilogue: bias, fp16 pair store, fused stats ----
    if (tid < 128) sred[tid] = 0.0f;
    float s4[4] = {0,0,0,0}, q4[4] = {0,0,0,0};
    #pragma unroll
    for (int mt = 0; mt < 2; mt++) {
        int ocA = mw*32 + mt*16 + gQ;
        float bA = bias[ocA], bC = bias[ocA + 8];
        int cp = (mw*2 + mt)*8 + gQ;
        #pragma unroll
        for (int dsel = 0; dsel < 2; dsel++) {
            __half2* o = outp + (((size_t)(b*32 + cp)) << 19)
                              + (size_t)(d0 + dsel)*HW + h*WW_;
            #pragma unroll
            for (int nt = 0; nt < 4; nt++) {
                float* A = acc[mt][dsel*4 + nt];
                int w = nt*8 + tQ*2;
                float v0 = A[0] + bA;
                float v1 = A[1] + bA;
                float v2 = A[2] + bC;
                float v3 = A[3] + bC;
                o[w]     = __floats2half2_rn(v0, v2);
                o[w + 1] = __floats2half2_rn(v1, v3);
                s4[mt*2]   += v0 + v1;  q4[mt*2]   += v0*v0 + v1*v1;
                s4[mt*2+1] += v2 + v3;  q4[mt*2+1] += v2*v2 + v3*v3;
            }
        }
    }
    if (!PROF) {
        __syncthreads();
        #pragma unroll
        for (int mt = 0; mt < 2; mt++)
            #pragma unroll
            for (int half = 0; half < 2; half++) {
                int oc = mw*32 + mt*16 + gQ + half*8;
                atomicAdd(&sred[oc],      s4[mt*2 + half]);
                atomicAdd(&sred[64 + oc], q4[mt*2 + half]);
            }
        __syncthreads();
        if (tid < 64) {
            atomicAdd(&g_sum[STAGE + 1][tid],   sred[tid]);
            atomicAdd(&g_sumsq[STAGE + 1][tid], sred[64 + tid]);
        }
    }
}

// ---------------- BN stats -> scale/shift ----------------
__global__ void finalize_kernel(const float* __restrict__ gamma, const float* __restrict__ beta,
                                int C, int stage) {
    int c = threadIdx.x;
    if (c < C) {
        const float invM = 1.0f / 1048576.0f;   // B*D*H*W
        float mean = g_sum[stage][c] * invM;
        float var  = g_sumsq[stage][c] * invM - mean * mean;
        float sc = gamma[c] * rsqrtf(var + EPSB);
        g_scale[stage][c] = sc;
        g_shift[stage][c] = beta[c] - mean * sc;
    }
}

// ---------------- bn3 + relu + max over D (reads fp16 pairs) ----------------
__global__ void bevmax_kernel(float* __restrict__ out) {
    int t = blockIdx.x * blockDim.x + threadIdx.x;   // (b, cp 32, h, w)
    int w = t & 31; int hh = (t >> 5) & 127; int cp = (t >> 12) & 31; int b = t >> 17;
    const __half2* p = g_x3h + (((size_t)(b*32 + cp)) << 19) + hh*WW_ + w;
    float mxa = -1e30f, mna = 1e30f, mxb = -1e30f, mnb = 1e30f;
    #pragma unroll 4
    for (int d = 0; d < DD; d++) {
        __half2 v = p[(size_t)d*HW];
        float fa = __low2float(v), fb = __high2float(v);
        mxa = fmaxf(mxa, fa); mna = fminf(mna, fa);
        mxb = fmaxf(mxb, fb); mnb = fminf(mnb, fb);
    }
    int ca = ((cp >> 3) << 4) + (cp & 7);
    int cb = ca + 8;
    float sa = g_scale[2][ca], ha = g_shift[2][ca];
    float sb = g_scale[2][cb], hb = g_shift[2][cb];
    float va = (sa >= 0.0f) ? fmaf(sa, mxa, ha) : fmaf(sa, mna, ha);
    float vb = (sb >= 0.0f) ? fmaf(sb, mxb, hb) : fmaf(sb, mnb, hb);
    int sp = hh*WW_ + w;
    out[((size_t)(b*64 + ca) << 12) + sp] = fmaxf(va, 0.0f);
    out[((size_t)(b*64 + cb) << 12) + sp] = fmaxf(vb, 0.0f);
}

// ---------------- launch ----------------
extern "C" void kernel_launch(void* const* d_in, const int* in_sizes, int n_in,
                              void* d_out, int out_size) {
    const float* pc  = (const float*)d_in[0];
    const float* w1  = (const float*)d_in[1];
    const float* b1  = (const float*)d_in[2];
    const float* g1  = (const float*)d_in[3];
    const float* be1 = (const float*)d_in[4];
    const float* w2  = (const float*)d_in[5];
    const float* b2  = (const float*)d_in[6];
    const float* g2  = (const float*)d_in[7];
    const float* be2 = (const float*)d_in[8];
    const float* w3  = (const float*)d_in[9];
    const float* b3  = (const float*)d_in[10];
    const float* g3  = (const float*)d_in[11];
    const float* be3 = (const float*)d_in[12];
    float* out = (float*)d_out;
    int N = in_sizes[0] / (BB * 3);

    const int SMEM = 2*4*6*8*40*4;   // 61440 B
    cudaFuncSetAttribute(conv_mma<32,false>, cudaFuncAttributeMaxDynamicSharedMemorySize, SMEM);
    cudaFuncSetAttribute(conv_mma<64,false>, cudaFuncAttributeMaxDynamicSharedMemorySize, SMEM);
    cudaFuncSetAttribute(conv_mma<32,true>,  cudaFuncAttributeMaxDynamicSharedMemorySize, SMEM);

    zero_kernel<<<(BB*DHW + 255)/256, 256>>>();                      // launch 0
    min_kernel<<<6, 256>>>(pc, N);                                   // launch 1
    scatter_kernel<<<(BB*N + 255)/256, 256>>>(pc, N);                // launch 2

    // launch 3 — sacrificial tiny conv_mma instance so ncu (which captures user
    // launch #3) finally profiles the conv kernel. 64 CTAs, scratch output,
    // no stats side effects; ~60-80us.
    conv_mma<32,true><<<dim3(1, HH_/4, BB), 256, SMEM>>>(b2);

    prep_kernel<<<(27*64*16 + 255)/256, 256>>>(w2, 32, 0);
    prep_kernel<<<(27*64*32 + 255)/256, 256>>>(w3, 64, W2_SZ);

    conv1_kernel<<<dim3(DD, HH_/8, BB), 256>>>(w1, b1);
    finalize_kernel<<<1, 64>>>(g1, be1, 32, 0);
    bnrelu_kernel<<<(int)(((size_t)BB*16 << 17) / 256), 256>>>(0);

    conv_mma<32,false><<<dim3(DD/2, HH_/4, BB), 256, SMEM>>>(b2);
    finalize_kernel<<<1, 64>>>(g2, be2, 64, 1);
    bnrelu_kernel<<<(int)(((size_t)BB*32 << 17) / 256), 256>>>(1);

    conv_mma<64,false><<<dim3(DD/2, HH_/4, BB), 256, SMEM>>>(b3);
    finalize_kernel<<<1, 64>>>(g3, be3, 64, 2);

    bevmax_kernel<<<(BB*32*HW + 255)/256, 256>>>(out);
}

// round 16
// speedup vs baseline: 1.2223x; 1.2223x over previous
#include <cuda_runtime.h>
#include <cuda_fp16.h>
#include <math.h>

#define DD 128
#define HH_ 128
#define WW_ 32
#define DHW (128*128*32)   // 524288 = 2^19
#define HW  (128*32)       // 4096
#define BB 2
#define EPSB 1e-5f

// ---------------- scratch (device globals; no allocations allowed) ----------------
__device__ float   g_occ[BB*DHW];
__device__ __align__(16) __half2 g_x1h[(size_t)BB*16*DHW];   // conv1 out, pair (c, c+8); bn applied in-place later
__device__ __align__(16) __half2 g_x2h[(size_t)BB*32*DHW];   // conv2 out, pair-interleaved
__device__ __align__(16) __half2 g_x3h[(size_t)BB*32*DHW];   // conv3 raw out (also sacrificial-profile scratch)
__device__ float g_min[6];
__device__ float g_sum[3][64];
__device__ float g_sumsq[3][64];
__device__ float g_scale[3][64];
__device__ float g_shift[3][64];

// split-fp16 weights, fragment layout. conv2 at 0, conv3 at W2_SZ.
#define W2_SZ (27*64*16)
#define W3_SZ (27*64*32)
__device__ unsigned int g_whi[W2_SZ + W3_SZ];
__device__ unsigned int g_wlo[W2_SZ + W3_SZ];

// ---------------- small helpers ----------------
__device__ __forceinline__ void cp16(unsigned int* dst_smem, const void* src_gmem) {
    unsigned int s = (unsigned int)__cvta_generic_to_shared(dst_smem);
    asm volatile("cp.async.cg.shared.global [%0], [%1], 16;" :: "r"(s), "l"(src_gmem));
}

__device__ __forceinline__ void mma_f16(float& c0, float& c1, float& c2, float& c3,
                                        unsigned int a0, unsigned int a1,
                                        unsigned int a2, unsigned int a3,
                                        unsigned int b0, unsigned int b1) {
    asm volatile("mma.sync.aligned.m16n8k16.row.col.f32.f16.f16.f32 "
                 "{%0,%1,%2,%3}, {%4,%5,%6,%7}, {%8,%9}, {%0,%1,%2,%3};"
                 : "+f"(c0), "+f"(c1), "+f"(c2), "+f"(c3)
                 : "r"(a0), "r"(a1), "r"(a2), "r"(a3), "r"(b0), "r"(b1));
}

// ---------------- zero occupancy + stats accumulators ----------------
__global__ void zero_kernel() {
    int t = blockIdx.x * blockDim.x + threadIdx.x;
    if (t < BB*DHW) g_occ[t] = 0.0f;
    if (t < 192) { g_sum[t/64][t%64] = 0.0f; g_sumsq[t/64][t%64] = 0.0f; }
}

// ---------------- per (b,dim) min over N points (NaN -> 0) ----------------
__global__ void min_kernel(const float* __restrict__ pc, int N) {
    __shared__ float s[256];
    int id = blockIdx.x;
    const float* p = pc + (size_t)id * N;
    float m = 1e30f;
    for (int i = threadIdx.x; i < N; i += 256) {
        float v = p[i];
        if (v != v) v = 0.0f;
        m = fminf(m, v);
    }
    s[threadIdx.x] = m; __syncthreads();
    for (int k = 128; k > 0; k >>= 1) {
        if (threadIdx.x < k) s[threadIdx.x] = fminf(s[threadIdx.x], s[threadIdx.x + k]);
        __syncthreads();
    }
    if (threadIdx.x == 0) g_min[id] = s[0];
}

// ---------------- scatter points into occupancy grid ----------------
__global__ void scatter_kernel(const float* __restrict__ pc, int N) {
    int t = blockIdx.x * blockDim.x + threadIdx.x;
    if (t >= BB * N) return;
    int b = t / N, j = t - b * N;
    const float* p = pc + (size_t)b * 3 * N;
    float x = p[j];       if (x != x) x = 0.0f;
    float y = p[N + j];   if (y != y) y = 0.0f;
    float z = p[2*N + j]; if (z != z) z = 0.0f;
    int ix = (int)floorf((x - g_min[b*3+0]) * 16.0f);
    int iy = (int)floorf((y - g_min[b*3+1]) * 16.0f);
    int iz = (int)floorf((z - g_min[b*3+2]) * 16.0f);
    ix = min(max(ix, 0), 127);
    iy = min(max(iy, 0), 127);
    iz = min(max(iz, 0), 31);
    g_occ[b*DHW + ix*HW + iy*WW_ + iz] = 1.0f;
}

// ---------------- conv1: 1 -> 32, fp32, fused stats, fp16 pair output ----------------
__global__ void conv1_kernel(const float* __restrict__ w1, const float* __restrict__ b1) {
    __shared__ float sIn[3][10][35];
    __shared__ float sW[27][32];
    __shared__ float sB[32];
    __shared__ float c1red[128];
    int d = blockIdx.x, h0 = blockIdx.y * 8, b = blockIdx.z;
    int tid = threadIdx.x;
    for (int i = tid; i < 32*27; i += 256) { int oc = i/27, tap = i%27; sW[tap][oc] = w1[i]; }
    if (tid < 32) sB[tid] = b1[tid];
    if (tid < 128) c1red[tid] = 0.0f;
    for (int i = tid; i < 3*10*34; i += 256) {
        int ww = i % 34; int r = i / 34; int hh = r % 10; int kd = r / 10;
        int gd = d + kd - 1, gh = h0 + hh - 1, gw = ww - 1;
        float v = 0.0f;
        if (gd >= 0 && gd < DD && gh >= 0 && gh < HH_ && gw >= 0 && gw < WW_)
            v = g_occ[b*DHW + gd*HW + gh*WW_ + gw];
        sIn[kd][hh][ww] = v;
    }
    __syncthreads();
    int tx = tid & 31, ty = tid >> 5;
    float acc[32];
    #pragma unroll
    for (int oc = 0; oc < 32; oc++) acc[oc] = sB[oc];
    #pragma unroll
    for (int kd = 0; kd < 3; kd++)
    #pragma unroll
    for (int kh = 0; kh < 3; kh++) {
        float a0 = sIn[kd][ty+kh][tx], a1 = sIn[kd][ty+kh][tx+1], a2 = sIn[kd][ty+kh][tx+2];
        int t0 = kd*9 + kh*3;
        #pragma unroll
        for (int oc = 0; oc < 32; oc++)
            acc[oc] = fmaf(a0, sW[t0][oc], fmaf(a1, sW[t0+1][oc], fmaf(a2, sW[t0+2][oc], acc[oc])));
    }
    size_t sp = (size_t)d*HW + (h0+ty)*WW_ + tx;
    #pragma unroll
    for (int cp = 0; cp < 16; cp++) {
        int ch = ((cp >> 3) << 4) + (cp & 7);
        g_x1h[(((size_t)(b*16 + cp)) << 19) + sp] = __floats2half2_rn(acc[ch], acc[ch + 8]);
    }
    #pragma unroll
    for (int oc = 0; oc < 32; oc++) {
        atomicAdd(&c1red[oc], acc[oc]);
        atomicAdd(&c1red[64 + oc], acc[oc]*acc[oc]);
    }
    __syncthreads();
    if (tid < 32) {
        atomicAdd(&g_sum[0][tid], c1red[tid]);
        atomicAdd(&g_sumsq[0][tid], c1red[64 + tid]);
    }
}

// ---------------- weight prep: fp32 -> split fp16 (hi+lo), fragment layout ----------------
// k within 16-chunk: k = 2*pp + e  <->  channel = kc*16 + pp + 8*e
// slot = kc*8 + (ppl%4)*2 + ppl/4  so LDG.64 at slot 2t gives pairs t and t+4
__global__ void prep_kernel(const float* __restrict__ w, int CIN, int base) {
    int t = blockIdx.x * blockDim.x + threadIdx.x;
    int CINP = CIN >> 1;
    int total = 27 * 64 * CINP;
    if (t >= total) return;
    int p   = t % CINP;
    int oc  = (t / CINP) % 64;
    int tap = t / (CINP * 64);
    int kc = p >> 3, ppl = p & 7;
    int slot = kc*8 + (ppl & 3)*2 + (ppl >> 2);
    int cl = kc*16 + ppl;
    int ch = cl + 8;
    float v0 = w[((size_t)oc*CIN + cl)*27 + tap];
    float v1 = w[((size_t)oc*CIN + ch)*27 + tap];
    __half h0 = __float2half_rn(v0);
    __half h1 = __float2half_rn(v1);
    __half l0 = __float2half_rn(v0 - __half2float(h0));
    __half l1 = __float2half_rn(v1 - __half2float(h1));
    unsigned int idx = base + (tap*64 + oc)*CINP + slot;
    __half2 hh = __halves2half2(h0, h1);
    __half2 ll = __halves2half2(l0, l1);
    g_whi[idx] = *reinterpret_cast<unsigned int*>(&hh);
    g_wlo[idx] = *reinterpret_cast<unsigned int*>(&ll);
}

// ---------------- standalone bn+relu (in-place on fp16 pair tensors) ----------------
__global__ void bnrelu_kernel(int stage) {
    __half2* x = (stage == 0) ? g_x1h : g_x2h;
    int CP = (stage == 0) ? 16 : 32;
    size_t t = (size_t)blockIdx.x * 256 + threadIdx.x;   // uint4 (=4 half2) index
    size_t total4 = ((size_t)BB * CP) << 17;
    if (t >= total4) return;
    int cp = (int)((t >> 17) % CP);
    int ca = ((cp >> 3) << 4) + (cp & 7), cb = ca + 8;
    float sa = g_scale[stage][ca], ha = g_shift[stage][ca];
    float sb = g_scale[stage][cb], hb = g_shift[stage][cb];
    uint4* p4 = reinterpret_cast<uint4*>(x) + t;
    uint4 raw = *p4;
    unsigned int* u = reinterpret_cast<unsigned int*>(&raw);
    #pragma unroll
    for (int i = 0; i < 4; i++) {
        __half2 v = *reinterpret_cast<__half2*>(&u[i]);
        float fa = fmaxf(fmaf(__low2float(v),  sa, ha), 0.0f);
        float fb = fmaxf(fmaf(__high2float(v), sb, hb), 0.0f);
        __half2 o = __floats2half2_rn(fa, fb);
        u[i] = *reinterpret_cast<unsigned int*>(&o);
    }
    *p4 = raw;
}

// ---------------- chunk fill: pure cp.async copies (input is post-bn fp16) ----------------
// buf layout: [plane 4][h 6][pair 8][40]; data at w-index gw+4 (gw 0..31), borders stay zero.
template<int CPIN>
__device__ __forceinline__ void fill_chunk(unsigned int* buf, const __half2* in,
                                           int b, int kk, int d0, int h0, int tid) {
    #pragma unroll
    for (int k = 0; k < 6; k++) {
        int i = tid + k*256;            // 0..1535
        int j = i & 7;                  // 16B chunk within row
        int r = i >> 3;                 // row 0..191
        int pp = r & 7;
        int hh = (r >> 3) % 6;
        int pd = r / 48;
        int gd = d0 - 1 + pd, gh = h0 + hh - 1;
        if ((unsigned)gd < DD && (unsigned)gh < HH_) {
            const __half2* src = in + (((size_t)(b*CPIN + kk*8 + pp)) << 19)
                                    + (size_t)gd*HW + gh*WW_ + j*4;
            cp16(buf + r*40 + 4 + j*4, src);
        }
    }
}

// ---------------- conv2/conv3: fp16 2-MMA implicit GEMM, 2 d-planes per CTA ----------------
// Block: (d0..d0+1, 4 h-rows, b), all 64 oc. 8 warps = 2 oc-warps x 4 h-warps.
// __launch_bounds__(256, 2): cap regs at 128 so 2 CTAs (16 warps, 4/SMSP) are resident —
// R13 profile showed 1 CTA/SM (regs 132) with issue_active only ~36% on active SMs.
// PROF=true: tiny sacrificial instance for ncu capture (launch idx 3) — writes to g_x3h scratch
// (fully overwritten by the real conv3 later), no stats atomics. Zero effect on results.
template<int CIN, bool PROF>
__global__ void __launch_bounds__(256, 2) conv_mma(const float* __restrict__ bias) {
    constexpr int STAGE = (CIN == 32) ? 0 : 1;
    constexpr int CPIN  = CIN / 2;
    constexpr int NCH   = CIN / 16;
    constexpr int WBASE = (CIN == 32) ? 0 : W2_SZ;
    constexpr int BUFSZ = 4*6*8*40;                 // 7680 u32
    const __half2* in  = (CIN == 32) ? g_x1h : g_x2h;
    __half2*       outp = PROF ? g_x3h : ((CIN == 32) ? g_x2h : g_x3h);

    extern __shared__ unsigned int sAct[];          // [2][BUFSZ]
    __shared__ float sred[128];

    int d0 = blockIdx.x * 2;
    int h0 = blockIdx.y * 4;
    int b  = blockIdx.z;
    int tid = threadIdx.x, lane = tid & 31, wid = tid >> 5;
    int mw = wid & 1, hw = wid >> 1;
    int gQ = lane >> 2, tQ = lane & 3;
    int h = h0 + hw;

    // zero both buffers once (covers padding rows/borders forever)
    for (int i = tid; i < 2*BUFSZ; i += 256) sAct[i] = 0u;
    __syncthreads();

    // prologue: fill chunk 0 into buffer 0
    fill_chunk<CPIN>(sAct, in, b, 0, d0, h0, tid);
    asm volatile("cp.async.commit_group;" ::: "memory");
    asm volatile("cp.async.wait_group 0;" ::: "memory");
    __syncthreads();

    float acc[2][8][4];
    #pragma unroll
    for (int mt = 0; mt < 2; mt++)
        #pragma unroll
        for (int s = 0; s < 8; s++)
            #pragma unroll
            for (int k = 0; k < 4; k++) acc[mt][s][k] = 0.0f;

    #pragma unroll 1
    for (int kk = 0; kk < NCH; kk++) {
        unsigned int* buf = sAct + (kk & 1) * BUFSZ;
        if (kk + 1 < NCH)
            fill_chunk<CPIN>(sAct + ((kk + 1) & 1) * BUFSZ, in, b, kk + 1, d0, h0, tid);
        asm volatile("cp.async.commit_group;" ::: "memory");

        #pragma unroll 1
        for (int kd = 0; kd < 3; kd++) {
            #pragma unroll 1
            for (int kh = 0; kh < 3; kh++) {
                #pragma unroll
                for (int kw = 0; kw < 3; kw++) {
                    int tap = (kd*3 + kh)*3 + kw;
                    // B fragments: 8 slots = 2 dsel x 4 nt
                    unsigned int bf0[8], bf1[8];
                    #pragma unroll
                    for (int dsel = 0; dsel < 2; dsel++) {
                        const unsigned int* row = buf + ((dsel + kd)*6 + hw + kh)*320;
                        #pragma unroll
                        for (int nt = 0; nt < 4; nt++) {
                            int idx = tQ*40 + nt*8 + gQ + kw + 3;
                            bf0[dsel*4 + nt] = row[idx];
                            bf1[dsel*4 + nt] = row[idx + 160];   // pair + 4
                        }
                    }
                    // A fragments (weights): loaded once, reused for both d
                    uint2 ah[2][2], al[2][2];
                    #pragma unroll
                    for (int mt = 0; mt < 2; mt++) {
                        int oc = mw*32 + mt*16 + gQ;
                        unsigned int widx = WBASE + (tap*64 + oc)*CPIN + kk*8 + tQ*2;
                        ah[mt][0] = *(const uint2*)&g_whi[widx];
                        ah[mt][1] = *(const uint2*)&g_whi[widx + 8*CPIN];
                        al[mt][0] = *(const uint2*)&g_wlo[widx];
                        al[mt][1] = *(const uint2*)&g_wlo[widx + 8*CPIN];
                    }
                    // 16 hi MMAs then 16 lo MMAs (max RAW gap on each acc)
                    #pragma unroll
                    for (int mt = 0; mt < 2; mt++)
                        #pragma unroll
                        for (int s = 0; s < 8; s++) {
                            float* A = acc[mt][s];
                            mma_f16(A[0], A[1], A[2], A[3],
                                    ah[mt][0].x, ah[mt][1].x, ah[mt][0].y, ah[mt][1].y,
                                    bf0[s], bf1[s]);
                        }
                    #pragma unroll
                    for (int mt = 0; mt < 2; mt++)
                        #pragma unroll
                        for (int s = 0; s < 8; s++) {
                            float* A = acc[mt][s];
                            mma_f16(A[0], A[1], A[2], A[3],
                                    al[mt][0].x, al[mt][1].x, al[mt][0].y, al[mt][1].y,
                                    bf0[s], bf1[s]);
                        }
                }
            }
        }
        asm volatile("cp.async.wait_group 0;" ::: "memory");
        __syncthreads();
    }

    // ---- epilogue: bias, fp16 pair store, fused stats ----
    if (tid < 128) sred[tid] = 0.0f;
    float s4[4] = {0,0,0,0}, q4[4] = {0,0,0,0};
    #pragma unroll
    for (int mt = 0; mt < 2; mt++) {
        int ocA = mw*32 + mt*16 + gQ;
        float bA = bias[ocA], bC = bias[ocA + 8];
        int cp = (mw*2 + mt)*8 + gQ;
        #pragma unroll
        for (int dsel = 0; dsel < 2; dsel++) {
            __half2* o = outp + (((size_t)(b*32 + cp)) << 19)
                              + (size_t)(d0 + dsel)*HW + h*WW_;
            #pragma unroll
            for (int nt = 0; nt < 4; nt++) {
                float* A = acc[mt][dsel*4 + nt];
                int w = nt*8 + tQ*2;
                float v0 = A[0] + bA;
                float v1 = A[1] + bA;
                float v2 = A[2] + bC;
                float v3 = A[3] + bC;
                o[w]     = __floats2half2_rn(v0, v2);
                o[w + 1] = __floats2half2_rn(v1, v3);
                s4[mt*2]   += v0 + v1;  q4[mt*2]   += v0*v0 + v1*v1;
                s4[mt*2+1] += v2 + v3;  q4[mt*2+1] += v2*v2 + v3*v3;
            }
        }
    }
    if (!PROF) {
        __syncthreads();
        #pragma unroll
        for (int mt = 0; mt < 2; mt++)
            #pragma unroll
            for (int half = 0; half < 2; half++) {
                int oc = mw*32 + mt*16 + gQ + half*8;
                atomicAdd(&sred[oc],      s4[mt*2 + half]);
                atomicAdd(&sred[64 + oc], q4[mt*2 + half]);
            }
        __syncthreads();
        if (tid < 64) {
            atomicAdd(&g_sum[STAGE + 1][tid],   sred[tid]);
            atomicAdd(&g_sumsq[STAGE + 1][tid], sred[64 + tid]);
        }
    }
}

// ---------------- BN stats -> scale/shift ----------------
__global__ void finalize_kernel(const float* __restrict__ gamma, const float* __restrict__ beta,
                                int C, int stage) {
    int c = threadIdx.x;
    if (c < C) {
        const float invM = 1.0f / 1048576.0f;   // B*D*H*W
        float mean = g_sum[stage][c] * invM;
        float var  = g_sumsq[stage][c] * invM - mean * mean;
        float sc = gamma[c] * rsqrtf(var + EPSB);
        g_scale[stage][c] = sc;
        g_shift[stage][c] = beta[c] - mean * sc;
    }
}

// ---------------- bn3 + relu + max over D (reads fp16 pairs) ----------------
__global__ void bevmax_kernel(float* __restrict__ out) {
    int t = blockIdx.x * blockDim.x + threadIdx.x;   // (b, cp 32, h, w)
    int w = t & 31; int hh = (t >> 5) & 127; int cp = (t >> 12) & 31; int b = t >> 17;
    const __half2* p = g_x3h + (((size_t)(b*32 + cp)) << 19) + hh*WW_ + w;
    float mxa = -1e30f, mna = 1e30f, mxb = -1e30f, mnb = 1e30f;
    #pragma unroll 4
    for (int d = 0; d < DD; d++) {
        __half2 v = p[(size_t)d*HW];
        float fa = __low2float(v), fb = __high2float(v);
        mxa = fmaxf(mxa, fa); mna = fminf(mna, fa);
        mxb = fmaxf(mxb, fb); mnb = fminf(mnb, fb);
    }
    int ca = ((cp >> 3) << 4) + (cp & 7);
    int cb = ca + 8;
    float sa = g_scale[2][ca], ha = g_shift[2][ca];
    float sb = g_scale[2][cb], hb = g_shift[2][cb];
    float va = (sa >= 0.0f) ? fmaf(sa, mxa, ha) : fmaf(sa, mna, ha);
    float vb = (sb >= 0.0f) ? fmaf(sb, mxb, hb) : fmaf(sb, mnb, hb);
    int sp = hh*WW_ + w;
    out[((size_t)(b*64 + ca) << 12) + sp] = fmaxf(va, 0.0f);
    out[((size_t)(b*64 + cb) << 12) + sp] = fmaxf(vb, 0.0f);
}

// ---------------- launch ----------------
extern "C" void kernel_launch(void* const* d_in, const int* in_sizes, int n_in,
                              void* d_out, int out_size) {
    const float* pc  = (const float*)d_in[0];
    const float* w1  = (const float*)d_in[1];
    const float* b1  = (const float*)d_in[2];
    const float* g1  = (const float*)d_in[3];
    const float* be1 = (const float*)d_in[4];
    const float* w2  = (const float*)d_in[5];
    const float* b2  = (const float*)d_in[6];
    const float* g2  = (const float*)d_in[7];
    const float* be2 = (const float*)d_in[8];
    const float* w3  = (const float*)d_in[9];
    const float* b3  = (const float*)d_in[10];
    const float* g3  = (const float*)d_in[11];
    const float* be3 = (const float*)d_in[12];
    float* out = (float*)d_out;
    int N = in_sizes[0] / (BB * 3);

    const int SMEM = 2*4*6*8*40*4;   // 61440 B  (x2 CTAs = 122.9KB < 227KB)
    cudaFuncSetAttribute(conv_mma<32,false>, cudaFuncAttributeMaxDynamicSharedMemorySize, SMEM);
    cudaFuncSetAttribute(conv_mma<64,false>, cudaFuncAttributeMaxDynamicSharedMemorySize, SMEM);
    cudaFuncSetAttribute(conv_mma<32,true>,  cudaFuncAttributeMaxDynamicSharedMemorySize, SMEM);

    zero_kernel<<<(BB*DHW + 255)/256, 256>>>();                      // launch 0
    min_kernel<<<6, 256>>>(pc, N);                                   // launch 1
    scatter_kernel<<<(BB*N + 255)/256, 256>>>(pc, N);                // launch 2

    // launch 3 — sacrificial tiny conv_mma instance so ncu (which captures user
    // launch #3) profiles the conv kernel. 64 CTAs, scratch output,
    // no stats side effects; verifies the 2-CTA occupancy fix.
    conv_mma<32,true><<<dim3(1, HH_/4, BB), 256, SMEM>>>(b2);

    prep_kernel<<<(27*64*16 + 255)/256, 256>>>(w2, 32, 0);
    prep_kernel<<<(27*64*32 + 255)/256, 256>>>(w3, 64, W2_SZ);

    conv1_kernel<<<dim3(DD, HH_/8, BB), 256>>>(w1, b1);
    finalize_kernel<<<1, 64>>>(g1, be1, 32, 0);
    bnrelu_kernel<<<(int)(((size_t)BB*16 << 17) / 256), 256>>>(0);

    conv_mma<32,false><<<dim3(DD/2, HH_/4, BB), 256, SMEM>>>(b2);
    finalize_kernel<<<1, 64>>>(g2, be2, 64, 1);
    bnrelu_kernel<<<(int)(((size_t)BB*32 << 17) / 256), 256>>>(1);

    conv_mma<64,false><<<dim3(DD/2, HH_/4, BB), 256, SMEM>>>(b3);
    finalize_kernel<<<1, 64>>>(g3, be3, 64, 2);

    bevmax_kernel<<<(BB*32*HW + 255)/256, 256>>>(out);
}